// round 6
// baseline (speedup 1.0000x reference)
#include <cuda_runtime.h>
#include <cuda_fp16.h>
#include <cstdint>

// CapsuleLayer: v = routing(reshape(x @ W, [B,16,32]))
//   x: [32768, 512] f32, W: [512, 512] f32, out v: [32768, 32] f32
//
// K1: split_W -> g_Wp  (hi/lo fp16 pairs, k-major, [kp][n])     (~1us)
// K2: split_X -> g_Xp  (hi/lo fp16 pairs, [row][kp])            (~18us)
// K3: GEMM u = hh + hl + lh via m16n8k16 HMMA, staging = pure copy
// K4: routing, shuffle-minimized (reduce-scatter + distributed softmax)

#define K_DIM 512
#define N_DIM 512
#define NUM_CAPS 16
#define OUT_DIM 32
#define MAX_BATCH 32768
#define NKPALL (K_DIM / 2)    // 256 k-pairs total

#define BM 128
#define BN 128
#define BK 16
#define NKP (BK / 2)          // 8 k-pairs per stage
#define XS_STRIDE (BM + 4)
#define WS_STRIDE (BN + 4)

// __device__ scratch (no allocation)
__device__ float g_u[(size_t)MAX_BATCH * N_DIM];                  // 64 MB
__device__ uint2 g_Xp[(size_t)MAX_BATCH * NKPALL];                // 64 MB
__device__ uint2 g_Wp[(size_t)NKPALL * N_DIM];                    // 2 MB

// split x into (hi, lo) fp16: hi = rn16(x), lo = rn16(x - hi)
__device__ __forceinline__ void split16(float x, __half& h, __half& l) {
    h = __float2half_rn(x);
    l = __float2half_rn(x - __half2float(h));
}

// pack two k-adjacent values (v0 = even k -> low half) into (hi2, lo2)
__device__ __forceinline__ uint2 pack_pair(float v0, float v1) {
    __half h0, l0, h1, l1;
    split16(v0, h0, l0);
    split16(v1, h1, l1);
    uint2 r;
    __half2 hh = __halves2half2(h0, h1);
    __half2 ll = __halves2half2(l0, l1);
    r.x = *reinterpret_cast<uint32_t*>(&hh);
    r.y = *reinterpret_cast<uint32_t*>(&ll);
    return r;
}

__device__ __forceinline__ void mma_m16n8k16_f16(float d[4], const uint32_t a[4],
                                                 const uint32_t b[2]) {
    asm volatile(
        "mma.sync.aligned.m16n8k16.row.col.f32.f16.f16.f32 "
        "{%0,%1,%2,%3}, {%4,%5,%6,%7}, {%8,%9}, {%0,%1,%2,%3};\n"
        : "+f"(d[0]), "+f"(d[1]), "+f"(d[2]), "+f"(d[3])
        : "r"(a[0]), "r"(a[1]), "r"(a[2]), "r"(a[3]), "r"(b[0]), "r"(b[1]));
}

// ---------------------------------------------------------------------------
// K1: W [512 k][512 n] f32 -> g_Wp [256 kp][512 n] uint2
// ---------------------------------------------------------------------------
__global__ void split_w_kernel(const float* __restrict__ W) {
    const int idx = blockIdx.x * blockDim.x + threadIdx.x;   // 131072 threads
    const int kp = idx >> 9;
    const int n = idx & 511;
    g_Wp[idx] = pack_pair(W[(size_t)(2 * kp) * N_DIM + n],
                          W[(size_t)(2 * kp + 1) * N_DIM + n]);
}

// ---------------------------------------------------------------------------
// K2: X [32768 row][512 k] f32 -> g_Xp [row][256 kp] uint2
// thread handles 8 consecutive k (4 kp): 32B in, 32B out, coalesced.
// ---------------------------------------------------------------------------
__global__ void split_x_kernel(const float* __restrict__ X) {
    const int idx = blockIdx.x * blockDim.x + threadIdx.x;   // 2M threads
    const int row = idx >> 6;
    const int seg = idx & 63;   // 8 k per seg
    const float4* src = reinterpret_cast<const float4*>(X + (size_t)row * K_DIM + seg * 8);
    float4 v0 = src[0];
    float4 v1 = src[1];
    uint2 p0 = pack_pair(v0.x, v0.y);
    uint2 p1 = pack_pair(v0.z, v0.w);
    uint2 p2 = pack_pair(v1.x, v1.y);
    uint2 p3 = pack_pair(v1.z, v1.w);
    uint4* dst = reinterpret_cast<uint4*>(&g_Xp[(size_t)row * NKPALL + seg * 4]);
    dst[0] = make_uint4(p0.x, p0.y, p1.x, p1.y);
    dst[1] = make_uint4(p2.x, p2.y, p3.x, p3.y);
}

// ---------------------------------------------------------------------------
// K3: GEMM C[M,512] = X @ W via FP16 split, m16n8k16 HMMA.
// Block tile 128x128, K-chunk 16, 256 threads (8 warps as 4(m) x 2(n)),
// warp tile 32x64 = 2(m16) x 8(n8) fragments. Staging = copy of pre-split data.
// ---------------------------------------------------------------------------
__global__ void __launch_bounds__(256, 2)
capsule_gemm_kernel() {
    __shared__ __align__(16) uint2 Xs[2][NKP][XS_STRIDE];   // 16.9 KB
    __shared__ __align__(16) uint2 Ws[2][NKP][WS_STRIDE];   // 16.9 KB

    const int tid = threadIdx.x;
    const int n0 = blockIdx.x * BN;   // n fast-varying -> X tile L2 reuse
    const int m0 = blockIdx.y * BM;

    const int warp = tid >> 5;
    const int lane = tid & 31;
    const int wm = warp >> 1;         // 0..3 -> 32 rows
    const int wn = warp & 1;          // 0..1 -> 64 cols
    const int g = lane >> 2;          // 0..7
    const int t = lane & 3;           // 0..3

    // A staging: row am (0..127), 4 kp at offset akp (0 or 4) -> 32B
    const int am  = tid >> 1;
    const int akp = (tid & 1) << 2;
    // B staging: kp row wkp (0..7), 4 n at wn4 -> 32B
    const int wkp = tid >> 5;
    const int wn4 = (tid & 31) << 2;

    float acc[2][8][4];
#pragma unroll
    for (int i = 0; i < 2; i++)
#pragma unroll
        for (int j = 0; j < 8; j++)
#pragma unroll
            for (int q = 0; q < 4; q++) acc[i][j][q] = 0.f;

    const uint4* Asrc = reinterpret_cast<const uint4*>(
        &g_Xp[(size_t)(m0 + am) * NKPALL + akp]);            // + kt*4 (uint4 units)
    const uint4* Bsrc = reinterpret_cast<const uint4*>(
        &g_Wp[(size_t)wkp * N_DIM + n0 + wn4]);              // + kt*8*256 (uint4 units)

    uint4 xa0, xa1, wb0, wb1;

    auto ldg_tiles = [&](int kt) {
        const uint4* a = Asrc + kt * 4;          // 8 kp = 4 uint4 per ktile
        xa0 = a[0];
        xa1 = a[1];
        const uint4* b = Bsrc + (size_t)kt * 8 * (N_DIM / 2);  // 8 kp rows
        wb0 = b[0];
        wb1 = b[1];
    };

    auto sts_tiles = [&](int buf) {
        Xs[buf][akp + 0][am] = make_uint2(xa0.x, xa0.y);
        Xs[buf][akp + 1][am] = make_uint2(xa0.z, xa0.w);
        Xs[buf][akp + 2][am] = make_uint2(xa1.x, xa1.y);
        Xs[buf][akp + 3][am] = make_uint2(xa1.z, xa1.w);
        *reinterpret_cast<uint4*>(&Ws[buf][wkp][wn4 + 0]) = wb0;
        *reinterpret_cast<uint4*>(&Ws[buf][wkp][wn4 + 2]) = wb1;
    };

    auto compute = [&](int buf) {
        uint32_t aH[2][4], aL[2][4];
#pragma unroll
        for (int i = 0; i < 2; i++) {
            const int mr = wm * 32 + i * 16 + g;
            uint2 A0 = Xs[buf][t][mr];
            uint2 A1 = Xs[buf][t][mr + 8];
            uint2 A2 = Xs[buf][t + 4][mr];
            uint2 A3 = Xs[buf][t + 4][mr + 8];
            aH[i][0] = A0.x; aL[i][0] = A0.y;
            aH[i][1] = A1.x; aL[i][1] = A1.y;
            aH[i][2] = A2.x; aL[i][2] = A2.y;
            aH[i][3] = A3.x; aL[i][3] = A3.y;
        }
#pragma unroll
        for (int j = 0; j < 8; j++) {
            const int nc = wn * 64 + j * 8 + g;
            uint2 B0 = Ws[buf][t][nc];
            uint2 B1 = Ws[buf][t + 4][nc];
            uint32_t bH[2] = {B0.x, B1.x};
            uint32_t bL[2] = {B0.y, B1.y};
#pragma unroll
            for (int i = 0; i < 2; i++) {
                mma_m16n8k16_f16(acc[i][j], aH[i], bH);  // hi*hi
                mma_m16n8k16_f16(acc[i][j], aH[i], bL);  // hi*lo
                mma_m16n8k16_f16(acc[i][j], aL[i], bH);  // lo*hi
            }
        }
    };

    ldg_tiles(0);
    sts_tiles(0);
    __syncthreads();

    const int NKT = K_DIM / BK;  // 32
    for (int kt = 0; kt < NKT; kt++) {
        const int buf = kt & 1;
        if (kt + 1 < NKT) ldg_tiles(kt + 1);
        compute(buf);
        if (kt + 1 < NKT) sts_tiles(buf ^ 1);
        __syncthreads();
    }

    // epilogue -> g_u
#pragma unroll
    for (int i = 0; i < 2; i++) {
#pragma unroll
        for (int j = 0; j < 8; j++) {
            const int row = m0 + wm * 32 + i * 16 + g;
            const int col = n0 + wn * 64 + j * 8 + t * 2;
            *reinterpret_cast<float2*>(&g_u[(size_t)row * N_DIM + col]) =
                make_float2(acc[i][j][0], acc[i][j][1]);
            *reinterpret_cast<float2*>(&g_u[(size_t)(row + 8) * N_DIM + col]) =
                make_float2(acc[i][j][2], acc[i][j][3]);
        }
    }
}

// ---------------------------------------------------------------------------
// K4: routing, one warp per row, lane = dim. Shuffle-minimized.
//   - 16 dot-products u[c].v via multi-value butterfly reduce-scatter (16 shfl)
//     lane l ends owning capsule cap = (l>>1)&15 (dup across lane pairs)
//   - distributed softmax: 1 exp/lane, butterflies over offsets 2,4,8,16
//   - capsule weights gathered by 16 shfl.idx
// ---------------------------------------------------------------------------
__device__ __forceinline__ float reduce_scatter16(float p[NUM_CAPS], int lane) {
    // o=16, m=16
    {
        const bool low = (lane & 16) == 0;
#pragma unroll
        for (int i = 0; i < 8; i++) {
            float send = low ? p[i + 8] : p[i];
            float recv = __shfl_xor_sync(0xffffffffu, send, 16);
            float keep = low ? p[i] : p[i + 8];
            p[i] = keep + recv;
        }
    }
    // o=8, m=8
    {
        const bool low = (lane & 8) == 0;
#pragma unroll
        for (int i = 0; i < 4; i++) {
            float send = low ? p[i + 4] : p[i];
            float recv = __shfl_xor_sync(0xffffffffu, send, 8);
            float keep = low ? p[i] : p[i + 4];
            p[i] = keep + recv;
        }
    }
    // o=4, m=4
    {
        const bool low = (lane & 4) == 0;
#pragma unroll
        for (int i = 0; i < 2; i++) {
            float send = low ? p[i + 2] : p[i];
            float recv = __shfl_xor_sync(0xffffffffu, send, 4);
            float keep = low ? p[i] : p[i + 2];
            p[i] = keep + recv;
        }
    }
    // o=2, m=2
    {
        const bool low = (lane & 2) == 0;
        float send = low ? p[1] : p[0];
        float recv = __shfl_xor_sync(0xffffffffu, send, 2);
        float keep = low ? p[0] : p[1];
        p[0] = keep + recv;
    }
    // o=1: lanes l, l^1 hold same capsule -> final sum over all 32 lanes
    return p[0] + __shfl_xor_sync(0xffffffffu, p[0], 1);
}

__device__ __forceinline__ float squash_scale(float s) {
    float norm = s * s;
#pragma unroll
    for (int o = 16; o; o >>= 1) norm += __shfl_xor_sync(0xffffffffu, norm, o);
    return (norm / (1.f + norm)) / (sqrtf(norm) + 1e-8f);
}

__global__ void __launch_bounds__(256)
capsule_routing_kernel(float* __restrict__ out, int batch) {
    const int gw = (int)((blockIdx.x * blockDim.x + threadIdx.x) >> 5);
    const int lane = threadIdx.x & 31;
    if (gw >= batch) return;

    const float* urow = g_u + (size_t)gw * N_DIM;
    float u[NUM_CAPS];
#pragma unroll
    for (int c = 0; c < NUM_CAPS; c++) u[c] = urow[c * OUT_DIM + lane];

    float bown = 0.f;   // logit of capsule (lane>>1)&15
    float v;

    // ---- iter 0: b = 0 -> uniform weights 1/16 ----
    {
        float s = u[0];
#pragma unroll
        for (int c = 1; c < NUM_CAPS; c++) s += u[c];
        s *= (1.f / 16.f);
        v = squash_scale(s) * s;

        float p[NUM_CAPS];
#pragma unroll
        for (int c = 0; c < NUM_CAPS; c++) p[c] = u[c] * v;
        bown += reduce_scatter16(p, lane);
    }

    // ---- iters 1, 2 ----
#pragma unroll
    for (int it = 1; it < 3; it++) {
        // distributed softmax over 16 capsules (each duplicated in lane pairs)
        float mx = bown;
#pragma unroll
        for (int o = 2; o <= 16; o <<= 1) mx = fmaxf(mx, __shfl_xor_sync(0xffffffffu, mx, o));
        float e = __expf(bown - mx);
        float sm = e;
#pragma unroll
        for (int o = 2; o <= 16; o <<= 1) sm += __shfl_xor_sync(0xffffffffu, sm, o);
        const float cw = e / sm;   // weight of my owned capsule

        // s[lane] = sum_c cw[c] * u[c][lane]; cw[c] lives at lane 2c
        float s = 0.f;
#pragma unroll
        for (int c = 0; c < NUM_CAPS; c++)
            s = fmaf(__shfl_sync(0xffffffffu, cw, 2 * c), u[c], s);

        v = squash_scale(s) * s;

        if (it < 2) {
            float p[NUM_CAPS];
#pragma unroll
            for (int c = 0; c < NUM_CAPS; c++) p[c] = u[c] * v;
            bown += reduce_scatter16(p, lane);
        }
    }

    out[(size_t)gw * OUT_DIM + lane] = v;
}

// ---------------------------------------------------------------------------
extern "C" void kernel_launch(void* const* d_in, const int* in_sizes, int n_in,
                              void* d_out, int out_size) {
    const float* X = (const float*)d_in[0];   // [batch, 512]
    const float* W = (const float*)d_in[1];   // [512, 512]
    float* out = (float*)d_out;               // [batch, 32]

    const int batch = in_sizes[0] / K_DIM;    // 32768

    split_w_kernel<<<(NKPALL * N_DIM) / 256, 256>>>(W);
    split_x_kernel<<<(batch * 64) / 256, 256>>>(X);

    dim3 ggrid(N_DIM / BN, batch / BM);       // (4, 256)
    capsule_gemm_kernel<<<ggrid, 256>>>();

    const int rthreads = batch * 32;
    capsule_routing_kernel<<<(rthreads + 255) / 256, 256>>>(out, batch);
}